// round 7
// baseline (speedup 1.0000x reference)
#include <cuda_runtime.h>

typedef unsigned long long u64;

#define BT  256   // threads per block
#define XPT 3     // vectors per thread
#define NP  128   // codeword pairs

// Packed codebook records: pair p = {ab0, ab1, cd0, cd1, q} (5 x u64)
__device__    u64 g_pack[NP * 5];
__constant__  u64 c_pack[NP * 5];

__device__ __forceinline__ u64 pk2(float lo, float hi) {
    u64 r;
    asm("mov.b64 %0, {%1, %2};" : "=l"(r) : "f"(lo), "f"(hi));
    return r;
}
__device__ __forceinline__ void upk2(u64 v, float& lo, float& hi) {
    asm("mov.b64 {%0, %1}, %2;" : "=f"(lo), "=f"(hi) : "l"(v));
}
// Blackwell packed fp32 FMA: d.lo = a.lo*b.lo + c.lo ; d.hi = a.hi*b.hi + c.hi
__device__ __forceinline__ u64 ffma2(u64 a, u64 b, u64 c) {
    u64 d;
    asm("fma.rn.f32x2 %0, %1, %2, %3;" : "=l"(d) : "l"(a), "l"(b), "l"(c));
    return d;
}
// ||c||^2 with a FIXED rounding order, used identically in prep and recovery.
__device__ __forceinline__ float qnorm(float4 a) {
    return __fmaf_rn(a.w, a.w, __fmaf_rn(a.z, a.z, __fmaf_rn(a.y, a.y, __fmul_rn(a.x, a.x))));
}

__global__ void pack_kernel(const float4* __restrict__ C) {
    const int t = threadIdx.x;
    if (t < NP) {
        float4 a = C[2 * t];
        float4 b = C[2 * t + 1];
        g_pack[5 * t + 0] = pk2(a.x, b.x);
        g_pack[5 * t + 1] = pk2(a.y, b.y);
        g_pack[5 * t + 2] = pk2(a.z, b.z);
        g_pack[5 * t + 3] = pk2(a.w, b.w);
        g_pack[5 * t + 4] = pk2(qnorm(a), qnorm(b));
    }
}

__global__ void __launch_bounds__(BT, 5)
vq_kernel(const float4* __restrict__ X,
          const float4* __restrict__ C,
          float4* __restrict__ outX,
          float* __restrict__ outS,
          int B)
{
    const int base = blockIdx.x * (BT * XPT) + threadIdx.x;

    u64 y0[XPT], y1[XPT], y2[XPT], y3[XPT];
    float bv[XPT];
    int   pid[XPT];

#pragma unroll
    for (int j = 0; j < XPT; j++) {
        int idx = base + j * BT;
        float4 x = (idx < B) ? X[idx] : make_float4(0.f, 0.f, 0.f, 0.f);
        float m0 = -2.0f * x.x, m1 = -2.0f * x.y, m2 = -2.0f * x.z, m3 = -2.0f * x.w;
        y0[j] = pk2(m0, m0);
        y1[j] = pk2(m1, m1);
        y2[j] = pk2(m2, m2);
        y3[j] = pk2(m3, m3);
        bv[j] = 3.402823466e38f;
        pid[j] = 0;
    }

    // Main loop: val_k = ||c_k||^2 - 2 x.c_k (same argmin as full distance).
    // Codebook comes from the constant bank (uniform datapath, no RF banks, no LDS).
#pragma unroll 4
    for (int p = 0; p < NP; p++) {
        const u64 ab0 = c_pack[5 * p + 0];
        const u64 ab1 = c_pack[5 * p + 1];
        const u64 cd0 = c_pack[5 * p + 2];
        const u64 cd1 = c_pack[5 * p + 3];
        const u64 q   = c_pack[5 * p + 4];
#pragma unroll
        for (int j = 0; j < XPT; j++) {
            u64 acc = ffma2(y0[j], ab0, q);
            acc = ffma2(y1[j], ab1, acc);
            acc = ffma2(y2[j], cd0, acc);
            acc = ffma2(y3[j], cd1, acc);
            float lo, hi;
            upk2(acc, lo, hi);
            float pv = fminf(lo, hi);
            if (pv < bv[j]) pid[j] = p;      // strict <: earlier pair wins ties
            bv[j] = fminf(bv[j], pv);        // FMNMX chain, lat 4
        }
    }

    // Recovery: reload the winning pair's raw rows from gmem (L1) and replay the
    // distance with a bitwise-identical scalar FFMA chain (lane semantics of ffma2).
    // hi<lo resolves the within-pair index; ties prefer lo (= smaller index),
    // matching jnp.argmin first-occurrence. The winner row doubles as the outX gather.
#pragma unroll
    for (int j = 0; j < XPT; j++) {
        const int p = pid[j];
        const float4 ca = C[2 * p];
        const float4 cb = C[2 * p + 1];
        const float qa = qnorm(ca);
        const float qb = qnorm(cb);
        float m0, m1, m2, m3, d_;
        upk2(y0[j], m0, d_); upk2(y1[j], m1, d_);
        upk2(y2[j], m2, d_); upk2(y3[j], m3, d_);
        float lo = __fmaf_rn(m3, ca.w, __fmaf_rn(m2, ca.z, __fmaf_rn(m1, ca.y, __fmaf_rn(m0, ca.x, qa))));
        float hi = __fmaf_rn(m3, cb.w, __fmaf_rn(m2, cb.z, __fmaf_rn(m1, cb.y, __fmaf_rn(m0, cb.x, qb))));
        const bool h = (hi < lo);
        const int bi = 2 * p + (h ? 1 : 0);
        const int idx = base + j * BT;
        if (idx < B) {
            outX[idx] = h ? cb : ca;
            outS[idx] = (float)bi;   // harness reads d_out as float32
        }
    }
}

extern "C" void kernel_launch(void* const* d_in, const int* in_sizes, int n_in,
                              void* d_out, int out_size)
{
    const float4* X = (const float4*)d_in[0];   // [B, 4] fp32
    const float4* C = (const float4*)d_in[1];   // [256, 4] fp32 codebook

    const int B = in_sizes[0] / 4;

    float4* outX = (float4*)d_out;                  // hatX [B,4] fp32
    float*  outS = (float*)d_out + 4 * (size_t)B;   // state [B] as fp32

    // 1) pack codebook pairs into a device buffer
    pack_kernel<<<1, 128>>>(C);

    // 2) stage packed records into the constant bank (D2D async, capturable)
    void* gp = nullptr;
    cudaGetSymbolAddress(&gp, g_pack);
    cudaMemcpyToSymbolAsync(c_pack, gp, sizeof(u64) * NP * 5, 0,
                            cudaMemcpyDeviceToDevice, 0);

    // 3) main kernel
    const int grid = (B + BT * XPT - 1) / (BT * XPT);
    vq_kernel<<<grid, BT>>>(X, C, outX, outS, B);
}

// round 8
// speedup vs baseline: 1.0330x; 1.0330x over previous
#include <cuda_runtime.h>

typedef unsigned long long u64;

#define BT  128   // threads per block
#define XPT 8     // vectors per thread: 8 independent chains/warp + 8x LDS amortization
#define NP  128   // codeword pairs

__device__ __forceinline__ u64 pk2(float lo, float hi) {
    u64 r;
    asm("mov.b64 %0, {%1, %2};" : "=l"(r) : "f"(lo), "f"(hi));
    return r;
}
__device__ __forceinline__ void upk2(u64 v, float& lo, float& hi) {
    asm("mov.b64 {%0, %1}, %2;" : "=f"(lo), "=f"(hi) : "l"(v));
}
// Blackwell packed fp32 FMA: d.lo = a.lo*b.lo + c.lo ; d.hi = a.hi*b.hi + c.hi
__device__ __forceinline__ u64 ffma2(u64 a, u64 b, u64 c) {
    u64 d;
    asm("fma.rn.f32x2 %0, %1, %2, %3;" : "=l"(d) : "l"(a), "l"(b), "l"(c));
    return d;
}

__global__ void __launch_bounds__(BT, 4)
vq_kernel(const float4* __restrict__ X,
          const float4* __restrict__ C,
          float4* __restrict__ outX,
          float* __restrict__ outS,
          int B)
{
    // Packed codebook, padded by 1 entry so the prefetch needs no guard.
    __shared__ ulonglong2 sAB[NP + 1];   // (dim0 pair, dim1 pair)
    __shared__ ulonglong2 sCD[NP + 1];   // (dim2 pair, dim3 pair)
    __shared__ u64        sQ [NP + 1];   // (||c||^2 pair)

    const int t = threadIdx.x;

    {
        // BT=128 == NP: one pair per thread
        float4 a = C[2 * t];
        float4 b = C[2 * t + 1];
        sAB[t] = make_ulonglong2(pk2(a.x, b.x), pk2(a.y, b.y));
        sCD[t] = make_ulonglong2(pk2(a.z, b.z), pk2(a.w, b.w));
        float qa = a.x * a.x + a.y * a.y + a.z * a.z + a.w * a.w;
        float qb = b.x * b.x + b.y * b.y + b.z * b.z + b.w * b.w;
        sQ[t] = pk2(qa, qb);
        if (t == 0) { sAB[NP] = sAB[0]; sCD[NP] = sCD[0]; sQ[NP] = sQ[0]; }
    }
    __syncthreads();

    const int base = blockIdx.x * (BT * XPT) + t;

    u64 y0[XPT], y1[XPT], y2[XPT], y3[XPT];
    float bv[XPT];
    int   pid[XPT];

#pragma unroll
    for (int j = 0; j < XPT; j++) {
        int idx = base + j * BT;
        float4 x = (idx < B) ? X[idx] : make_float4(0.f, 0.f, 0.f, 0.f);
        float m0 = -2.0f * x.x, m1 = -2.0f * x.y, m2 = -2.0f * x.z, m3 = -2.0f * x.w;
        y0[j] = pk2(m0, m0);
        y1[j] = pk2(m1, m1);
        y2[j] = pk2(m2, m2);
        y3[j] = pk2(m3, m3);
        bv[j] = 3.402823466e38f;
        pid[j] = 0;
    }

    // Main loop: val_k = ||c_k||^2 - 2 x.c_k (same argmin as full distance).
    // Software-pipelined: pair p+1's codebook regs load while pair p computes
    // (64 math inst per pair hide the 29-cyc LDS latency completely).
    ulonglong2 ab = sAB[0];
    ulonglong2 cd = sCD[0];
    u64        q  = sQ[0];
#pragma unroll 4
    for (int p = 0; p < NP; p++) {
        const ulonglong2 ab_n = sAB[p + 1];
        const ulonglong2 cd_n = sCD[p + 1];
        const u64        q_n  = sQ[p + 1];
#pragma unroll
        for (int j = 0; j < XPT; j++) {
            u64 acc = ffma2(y0[j], ab.x, q);
            acc = ffma2(y1[j], ab.y, acc);
            acc = ffma2(y2[j], cd.x, acc);
            acc = ffma2(y3[j], cd.y, acc);
            float lo, hi;
            upk2(acc, lo, hi);
            float pv = fminf(lo, hi);
            if (pv < bv[j]) pid[j] = p;      // strict <: earlier pair wins ties
            bv[j] = fminf(bv[j], pv);        // FMNMX chain, lat 4
        }
        ab = ab_n; cd = cd_n; q = q_n;
    }

    // Recovery: replay the winning pair's bitwise-identical FFMA2 chain (3 divergent
    // LDS per vector). FMNMX returns an input exactly, so hi<lo resolves the
    // within-pair index; ties prefer lo (= smaller index), matching jnp.argmin.
    // The winner's components come from the pair registers via SELs (no extra LDS).
#pragma unroll
    for (int j = 0; j < XPT; j++) {
        const int p = pid[j];
        const ulonglong2 rab = sAB[p];
        const ulonglong2 rcd = sCD[p];
        const u64        rq  = sQ[p];
        u64 acc = ffma2(y0[j], rab.x, rq);
        acc = ffma2(y1[j], rab.y, acc);
        acc = ffma2(y2[j], rcd.x, acc);
        acc = ffma2(y3[j], rcd.y, acc);
        float lo, hi;
        upk2(acc, lo, hi);
        const bool h = (hi < lo);
        float a0, b0, a1, b1, a2, b2, a3, b3;
        upk2(rab.x, a0, b0); upk2(rab.y, a1, b1);
        upk2(rcd.x, a2, b2); upk2(rcd.y, a3, b3);
        const int idx = base + j * BT;
        if (idx < B) {
            outX[idx] = make_float4(h ? b0 : a0, h ? b1 : a1,
                                    h ? b2 : a2, h ? b3 : a3);
            outS[idx] = (float)(2 * p + (h ? 1 : 0));   // harness reads d_out as f32
        }
    }
}

extern "C" void kernel_launch(void* const* d_in, const int* in_sizes, int n_in,
                              void* d_out, int out_size)
{
    const float4* X = (const float4*)d_in[0];   // [B, 4] fp32
    const float4* C = (const float4*)d_in[1];   // [256, 4] fp32 codebook

    const int B = in_sizes[0] / 4;

    float4* outX = (float4*)d_out;                  // hatX [B,4] fp32
    float*  outS = (float*)d_out + 4 * (size_t)B;   // state [B] as fp32

    const int grid = (B + BT * XPT - 1) / (BT * XPT);
    vq_kernel<<<grid, BT>>>(X, C, outX, outS, B);
}